// round 1
// baseline (speedup 1.0000x reference)
#include <cuda_runtime.h>
#include <cuda_bf16.h>
#include <math.h>

#define HDIM 64
#define CNEI 32
#define MAXSEQ 64
#define NBLK 32
#define NTHR 256
#define PEROWS 48

// ---- global scratch (no allocations allowed) ----
__device__ int   g_cnt = 0;
__device__ int   g_gen = 0;
__device__ float g_nxt[2][CNEI][HDIM];
__device__ float g_energy[2][CNEI];

__device__ __forceinline__ float gelu_exact(float v) {
    return 0.5f * v * (1.0f + erff(v / 1.4142135623730951f));
}

// Global barrier: sense via monotonically increasing generation counter.
// Last arriver resets count to 0 and bumps g_gen; g_gen never resets, so the
// pattern is safe across graph replays (every block reads its starting gen
// before ANY barrier can complete, since completion needs all 32 blocks).
__device__ __forceinline__ void gbar(int &mg) {
    __threadfence();
    __syncthreads();
    if (threadIdx.x == 0) {
        int old = atomicAdd(&g_cnt, 1);
        if (old == NBLK - 1) {
            *((volatile int*)&g_cnt) = 0;
            __threadfence();
            *((volatile int*)&g_gen) = mg + 1;
        } else {
            while (*((volatile int*)&g_gen) == mg) { }
        }
    }
    mg += 1;
    __syncthreads();
    __threadfence();
}

__global__ __launch_bounds__(NTHR, 1)
void bralm_kernel(const float* __restrict__ W,    // (E,64,64)
                  const float* __restrict__ B,    // (E,1,64)
                  const float* __restrict__ POS,  // (512,1)
                  const int*   __restrict__ SE,   // (L,)
                  const int*   __restrict__ NE,   // (N,C)
                  const int*   __restrict__ NN,   // (N,C)
                  const int*   __restrict__ X0P,  // scalar
                  const int*   __restrict__ MNTP, // scalar
                  float* __restrict__ out,
                  int out_size, int L)
{
    __shared__ float pe_s[PEROWS][HDIM];
    __shared__ float cache_s[MAXSEQ][HDIM];
    __shared__ float pos_s[MAXSEQ];
    __shared__ float wts_s[MAXSEQ];
    __shared__ float e_s[HDIM];
    __shared__ float red_s[4][HDIM];
    __shared__ float dt_s[HDIM / 2];
    __shared__ float sq_s[HDIM];
    __shared__ float en_s[CNEI];
    __shared__ int   tok_s[PEROWS];
    __shared__ int   x_sh, idx_sh, edge_sh;

    const int tid  = threadIdx.x;
    const int k    = tid & 63;
    const int part = tid >> 6;
    const int bx   = blockIdx.x;

    int my_gen = 0;
    if (tid == 0) my_gen = *((volatile int*)&g_gen);

    int T = (MNTP != nullptr) ? MNTP[0] : 32;
    if (T < 0) T = 0;
    if (L + T > MAXSEQ) T = MAXSEQ - L;
    if (T > PEROWS)     T = PEROWS;

    // div_term[j] = 10000 ** (2j/64), computed in double for bit-stable fp32
    if (tid < HDIM / 2)
        dt_s[tid] = (float)pow(10000.0, (double)(2 * tid) / 64.0);
    // zero cache
    for (int i = tid; i < MAXSEQ * HDIM; i += NTHR)
        cache_s[i >> 6][i & 63] = 0.0f;
    if (tid < MAXSEQ) pos_s[tid] = POS[tid];
    __syncthreads();

    // pe rows 0..47: pe[i,2j]=sin(i*dt[j]), pe[i,2j+1]=cos(i*dt[j]).
    // Arguments reach ~2.3e5, so range-reduce in double then take f32 sin/cos.
    for (int idx = tid; idx < PEROWS * HDIM; idx += NTHR) {
        int i = idx >> 6, h = idx & 63;
        float argf = (float)i * dt_s[h >> 1];        // fp32 product (matches ref)
        double ad = (double)argf;
        double kq = rint(ad * 0.15915494309189535);  // / (2*pi)
        double r  = fma(-kq, 6.283185307179586, ad);
        float rf  = (float)r;
        pe_s[i][h] = (h & 1) ? cosf(rf) : sinf(rf);
    }
    __syncthreads();

    // ---------------- prompt phase (redundant in every block) ----------------
    // step 0: e0 = ones/H
    if (tid < HDIM) e_s[k] = 1.0f / 64.0f;
    __syncthreads();

    for (int i = 0; i < L; ++i) {
        if (i > 0) {
            if (tid == 0) {
                float m = -INFINITY;
                for (int j = 0; j < i; ++j) m = fmaxf(m, pos_s[j]);
                float s = 0.0f;
                for (int j = 0; j < i; ++j) { float u = expf(pos_s[j] - m); wts_s[j] = u; s += u; }
                for (int j = 0; j < i; ++j) wts_s[j] = wts_s[j] / s;
            }
            __syncthreads();
            if (tid < HDIM) {
                float acc = 0.0f;
                for (int j = 0; j < i; ++j) acc = fmaf(wts_s[j], cache_s[j][k], acc);
                e_s[k] = acc;
            }
            __syncthreads();
        }
        // matvec: cache[i] = gelu(e @ W[se] + b[se] + pe[i])
        int edge = SE[i];
        const float* Wp = W + (long long)edge * (HDIM * HDIM);
        float acc = 0.0f;
        int h0 = part * 16;
        #pragma unroll
        for (int hh = 0; hh < 16; ++hh)
            acc = fmaf(e_s[h0 + hh], Wp[(h0 + hh) * HDIM + k], acc);
        red_s[part][k] = acc;
        __syncthreads();
        if (tid < HDIM) {
            float v = ((red_s[0][k] + red_s[1][k]) + red_s[2][k]) + red_s[3][k];
            v = v + B[(long long)edge * HDIM + k] + pe_s[i][k];
            cache_s[i][k] = gelu_exact(v);
        }
        __syncthreads();
    }

    // ---------------- generation phase ----------------
    if (tid == 0) x_sh = (X0P != nullptr) ? X0P[0] : 7;
    __syncthreads();

    for (int t = 0; t < T; ++t) {
        int curr = L + t;
        int buf  = t & 1;

        if (tid == 0) {
            float m = -INFINITY;
            for (int j = 0; j < curr; ++j) m = fmaxf(m, pos_s[j]);
            float s = 0.0f;
            for (int j = 0; j < curr; ++j) { float u = expf(pos_s[j] - m); wts_s[j] = u; s += u; }
            for (int j = 0; j < curr; ++j) wts_s[j] = wts_s[j] / s;
            edge_sh = NE[(long long)x_sh * CNEI + bx];
        }
        __syncthreads();

        if (tid < HDIM) {
            float acc = 0.0f;
            for (int j = 0; j < curr; ++j) acc = fmaf(wts_s[j], cache_s[j][k], acc);
            e_s[k] = acc;
        }
        __syncthreads();

        // candidate matvec for this block's neighbor edge
        {
            int edge = edge_sh;
            const float* Wp = W + (long long)edge * (HDIM * HDIM);
            float acc = 0.0f;
            int h0 = part * 16;
            #pragma unroll
            for (int hh = 0; hh < 16; ++hh)
                acc = fmaf(e_s[h0 + hh], Wp[(h0 + hh) * HDIM + k], acc);
            red_s[part][k] = acc;
            __syncthreads();
            if (tid < HDIM) {
                float v = ((red_s[0][k] + red_s[1][k]) + red_s[2][k]) + red_s[3][k];
                v = v + B[(long long)edge * HDIM + k] + pe_s[t][k];
                float g = gelu_exact(v);
                g_nxt[buf][bx][k] = g;
                sq_s[k] = g * g;
            }
            __syncthreads();
            if (tid < 32) {
                float s2 = sq_s[tid] + sq_s[tid + 32];
                #pragma unroll
                for (int off = 16; off > 0; off >>= 1)
                    s2 += __shfl_down_sync(0xffffffffu, s2, off);
                if (tid == 0) g_energy[buf][bx] = sqrtf(s2);
            }
        }

        gbar(my_gen);

        if (tid < CNEI) en_s[tid] = g_energy[buf][tid];
        __syncthreads();

        if (tid == 0) {
            // replicate softmax(energy) then first-occurrence argmax
            float m = -INFINITY;
            for (int i = 0; i < CNEI; ++i) m = fmaxf(m, en_s[i]);
            float s = 0.0f;
            for (int i = 0; i < CNEI; ++i) s += expf(en_s[i] - m);
            float best = -INFINITY; int bi = 0;
            for (int i = 0; i < CNEI; ++i) {
                float p = expf(en_s[i] - m) / s;
                if (p > best) { best = p; bi = i; }
            }
            idx_sh = bi;
            int y = NN[(long long)x_sh * CNEI + bi];
            tok_s[t] = y;
            x_sh = y;
        }
        __syncthreads();

        if (tid < HDIM) cache_s[curr][k] = g_nxt[buf][idx_sh][k];
        __syncthreads();
    }

    // ---------------- output (block 0) ----------------
    if (bx == 0) {
        int ncache = (L + T) * HDIM;
        for (int i = tid; i < out_size; i += NTHR) {
            float v;
            if (i < ncache) {
                v = cache_s[i >> 6][i & 63];
            } else {
                int tt = i - ncache;
                v = (tt < T) ? (float)tok_s[tt] : 0.0f;
            }
            out[i] = v;
        }
    }
}

extern "C" void kernel_launch(void* const* d_in, const int* in_sizes, int n_in,
                              void* d_out, int out_size) {
    const float* W   = (const float*)d_in[0];
    const float* B   = (const float*)d_in[1];
    const float* POS = (const float*)d_in[2];
    const int*   SE  = (const int*)d_in[3];
    const int*   NE  = (const int*)d_in[4];
    const int*   NN  = (const int*)d_in[5];
    const int*   X0  = (n_in > 6) ? (const int*)d_in[6] : nullptr;
    const int*   MNT = (n_in > 7) ? (const int*)d_in[7] : nullptr;
    int L = in_sizes[3];

    bralm_kernel<<<NBLK, NTHR>>>(W, B, POS, SE, NE, NN, X0, MNT,
                                 (float*)d_out, out_size, L);
}

// round 3
// speedup vs baseline: 2.8129x; 2.8129x over previous
#include <cuda_runtime.h>
#include <cstdint>
#include <stdint.h>
#include <math.h>

#define HDIM   64
#define CNEI   32
#define NBLK   8         // one cluster of 8 CTAs
#define CAND_PER 4       // candidates per CTA (8*4 = 32)
#define NTHR   512
#define PEROWS 48
#define MAXSEQ 64

__device__ __forceinline__ float gelu_exact(float v) {
    return 0.5f * v * (1.0f + erff(v * 0.70710678118654752440f));
}

__device__ __forceinline__ uint32_t mapa_u32(uint32_t addr, uint32_t rank) {
    uint32_t d;
    asm("mapa.shared::cluster.u32 %0, %1, %2;" : "=r"(d) : "r"(addr), "r"(rank));
    return d;
}
__device__ __forceinline__ void stc_f32(uint32_t addr, float v) {
    asm volatile("st.shared::cluster.f32 [%0], %1;" :: "r"(addr), "f"(v) : "memory");
}
__device__ __forceinline__ float ldc_f32(uint32_t addr) {
    float v;
    asm volatile("ld.shared::cluster.f32 %0, [%1];" : "=f"(v) : "r"(addr) : "memory");
    return v;
}
__device__ __forceinline__ void cluster_sync_all() {
    asm volatile("barrier.cluster.arrive.aligned;" ::: "memory");
    asm volatile("barrier.cluster.wait.aligned;"   ::: "memory");
}

__global__ __launch_bounds__(NTHR, 1) __cluster_dims__(NBLK, 1, 1)
void bralm_kernel(const float* __restrict__ W,    // (E,64,64)
                  const float* __restrict__ Bb,   // (E,1,64)
                  const float* __restrict__ POS,  // (512,1)
                  const int*   __restrict__ SE,   // (L,)
                  const int*   __restrict__ NE,   // (N,32)
                  const int*   __restrict__ NN,   // (N,32)
                  const int*   __restrict__ X0P,
                  const int*   __restrict__ MNTP,
                  float* __restrict__ out,
                  int out_size, int L)
{
    __shared__ float pe_s[PEROWS][HDIM];
    __shared__ float cache_s[MAXSEQ][HDIM];
    __shared__ float pos_s[MAXSEQ];
    __shared__ float wts_s[MAXSEQ];
    __shared__ float e_s[HDIM];
    __shared__ float red_s[8][HDIM];
    __shared__ float dt_s[HDIM / 2];
    __shared__ float sq_s[CAND_PER][HDIM];
    __shared__ float nxt_s[2][CAND_PER][HDIM];
    __shared__ float en_all[2][CNEI];
    __shared__ float en_own[CAND_PER];
    __shared__ int   tok_s[PEROWS];
    __shared__ int   edge_sh[CAND_PER];
    __shared__ int   x_sh, idx_sh;

    const int tid = threadIdx.x;
    uint32_t myrank;
    asm("mov.u32 %0, %%cluster_ctarank;" : "=r"(myrank));

    int T = (MNTP != nullptr) ? MNTP[0] : 32;
    if (T < 0) T = 0;
    if (L + T > MAXSEQ) T = MAXSEQ - L;
    if (T > PEROWS)     T = PEROWS;

    // ---- init: div_term, pos, cache zero, pe table ----
    if (tid < HDIM / 2)
        dt_s[tid] = (float)pow(10000.0, (double)(2 * tid) / 64.0);
    for (int i = tid; i < MAXSEQ * HDIM; i += NTHR)
        cache_s[i >> 6][i & 63] = 0.0f;
    if (tid < MAXSEQ) pos_s[tid] = POS[tid];
    __syncthreads();

    // pe[i,2j]=sin(i*dt[j]), pe[i,2j+1]=cos(i*dt[j]); fp32 product, double range-reduce
    for (int idx = tid; idx < PEROWS * HDIM; idx += NTHR) {
        int i = idx >> 6, h = idx & 63;
        float argf = (float)i * dt_s[h >> 1];
        double ad = (double)argf;
        double kq = rint(ad * 0.15915494309189535);
        double r  = fma(-kq, 6.283185307179586, ad);
        float rf  = (float)r;
        pe_s[i][h] = (h & 1) ? cosf(rf) : sinf(rf);
    }
    __syncthreads();

    // ---------------- prompt phase (redundant per CTA) ----------------
    if (tid < HDIM) e_s[tid] = 1.0f / 64.0f;
    __syncthreads();

    for (int i = 0; i < L; ++i) {
        if (i > 0) {
            // warp0: softmax weights over pos[0..i)
            if (tid < 32) {
                float m = -INFINITY;
                for (int j = tid; j < i; j += 32) m = fmaxf(m, pos_s[j]);
                #pragma unroll
                for (int off = 16; off > 0; off >>= 1)
                    m = fmaxf(m, __shfl_xor_sync(0xffffffffu, m, off));
                float s = 0.0f;
                for (int j = tid; j < i; j += 32) s += expf(pos_s[j] - m);
                #pragma unroll
                for (int off = 16; off > 0; off >>= 1)
                    s += __shfl_xor_sync(0xffffffffu, s, off);
                for (int j = tid; j < i; j += 32) wts_s[j] = expf(pos_s[j] - m) / s;
            }
            __syncthreads();
            { // pooled e: 8 parts over j
                int part = tid >> 6, k = tid & 63;
                float acc = 0.0f;
                for (int j = part; j < i; j += 8) acc = fmaf(wts_s[j], cache_s[j][k], acc);
                red_s[part][k] = acc;
            }
            __syncthreads();
            if (tid < HDIM) {
                float a = 0.0f;
                #pragma unroll
                for (int p = 0; p < 8; ++p) a += red_s[p][tid];
                e_s[tid] = a;
            }
            __syncthreads();
        }
        // matvec cache[i] = gelu(e @ W[se] + b + pe[i])
        int edge = SE[i];
        const float* Wp = W + (size_t)edge * (HDIM * HDIM);
        int part = tid >> 6, k = tid & 63;
        float acc = 0.0f;
        #pragma unroll
        for (int hh = 0; hh < 8; ++hh)
            acc = fmaf(e_s[part * 8 + hh], Wp[(part * 8 + hh) * HDIM + k], acc);
        red_s[part][k] = acc;
        __syncthreads();
        if (tid < HDIM) {
            float v = 0.0f;
            #pragma unroll
            for (int p = 0; p < 8; ++p) v += red_s[p][tid];
            v = v + Bb[(size_t)edge * HDIM + tid] + pe_s[i][tid];
            cache_s[i][tid] = gelu_exact(v);
        }
        __syncthreads();
    }

    // ---------------- generation phase ----------------
    if (tid == 0) x_sh = (X0P != nullptr) ? X0P[0] : 7;
    __syncthreads();
    if (tid < CAND_PER)
        edge_sh[tid] = NE[(size_t)x_sh * CNEI + myrank * CAND_PER + tid];
    __syncthreads();

    const int g    = tid >> 7;        // candidate 0..3
    const int tc   = tid & 127;
    const int k    = tc & 63;
    const int half = tc >> 6;         // 0..1 (rows half*32..half*32+31)

    for (int t = 0; t < T; ++t) {
        const int curr = L + t;
        const int buf  = t & 1;

        // 1) issue weight loads early (edge known from previous step)
        const float* Wp = W + (size_t)edge_sh[g] * (HDIM * HDIM) + (half * 32) * HDIM + k;
        float wreg[32];
        #pragma unroll
        for (int j = 0; j < 32; ++j) wreg[j] = Wp[j * HDIM];

        // 2) pos softmax (warp0) — overlaps with in-flight loads
        if (tid < 32) {
            float m = -INFINITY;
            for (int j = tid; j < curr; j += 32) m = fmaxf(m, pos_s[j]);
            #pragma unroll
            for (int off = 16; off > 0; off >>= 1)
                m = fmaxf(m, __shfl_xor_sync(0xffffffffu, m, off));
            float s = 0.0f;
            for (int j = tid; j < curr; j += 32) s += expf(pos_s[j] - m);
            #pragma unroll
            for (int off = 16; off > 0; off >>= 1)
                s += __shfl_xor_sync(0xffffffffu, s, off);
            for (int j = tid; j < curr; j += 32) wts_s[j] = expf(pos_s[j] - m) / s;
        }
        __syncthreads();

        // 3) pooled e
        {
            int part = tid >> 6, kk = tid & 63;
            float acc = 0.0f;
            for (int j = part; j < curr; j += 8) acc = fmaf(wts_s[j], cache_s[j][kk], acc);
            red_s[part][kk] = acc;
        }
        __syncthreads();
        if (tid < HDIM) {
            float a = 0.0f;
            #pragma unroll
            for (int p = 0; p < 8; ++p) a += red_s[p][tid];
            e_s[tid] = a;
        }
        __syncthreads();

        // 4) candidate matvec (consumes preloaded weights)
        {
            float acc = 0.0f;
            #pragma unroll
            for (int j = 0; j < 32; ++j)
                acc = fmaf(wreg[j], e_s[half * 32 + j], acc);
            red_s[g * 2 + half][k] = acc;
        }
        __syncthreads();
        if (tid < 256) {
            int gg = tid >> 6, kk = tid & 63;
            float v = red_s[gg * 2][kk] + red_s[gg * 2 + 1][kk]
                    + Bb[(size_t)edge_sh[gg] * HDIM + kk] + pe_s[t][kk];
            float ge = gelu_exact(v);
            nxt_s[buf][gg][kk] = ge;
            sq_s[gg][kk] = ge * ge;
        }
        __syncthreads();
        if (tid < 128) {
            int gg = tid >> 5, l = tid & 31;
            float s2 = sq_s[gg][l] + sq_s[gg][l + 32];
            #pragma unroll
            for (int off = 16; off > 0; off >>= 1)
                s2 += __shfl_xor_sync(0xffffffffu, s2, off);
            if (l == 0) en_own[gg] = sqrtf(s2);
        }
        __syncthreads();

        // 5) push our 4 energies to every CTA's en_all[buf]
        if (tid < 32) {
            int r = tid >> 2, c = tid & 3;
            uint32_t a = (uint32_t)__cvta_generic_to_shared(&en_all[buf][myrank * CAND_PER + c]);
            stc_f32(mapa_u32(a, (uint32_t)r), en_own[c]);
        }

        // 6) one cluster barrier per step
        cluster_sync_all();

        // 7) softmax->argmax over 32 energies (warp0), token + next edges
        if (tid < 32) {
            float en = en_all[buf][tid];
            float m = en;
            #pragma unroll
            for (int off = 16; off > 0; off >>= 1)
                m = fmaxf(m, __shfl_xor_sync(0xffffffffu, m, off));
            float u = expf(en - m);
            float s = u;
            #pragma unroll
            for (int off = 16; off > 0; off >>= 1)
                s += __shfl_xor_sync(0xffffffffu, s, off);
            float p = u / s;
            int bi = tid;
            #pragma unroll
            for (int off = 16; off > 0; off >>= 1) {
                float po = __shfl_xor_sync(0xffffffffu, p, off);
                int   io = __shfl_xor_sync(0xffffffffu, bi, off);
                if (po > p || (po == p && io < bi)) { p = po; bi = io; }
            }
            if (tid == 0) {
                idx_sh = bi;
                int y = NN[(size_t)x_sh * CNEI + bi];
                tok_s[t] = y;
                x_sh = y;
            }
        }
        __syncthreads();

        // 8) pull winning vector from winner CTA's smem; fetch next edges
        if (tid < HDIM) {
            int widx = idx_sh >> 2, slot = idx_sh & 3;
            uint32_t a = (uint32_t)__cvta_generic_to_shared(&nxt_s[buf][slot][tid]);
            cache_s[curr][tid] = ldc_f32(mapa_u32(a, (uint32_t)widx));
        } else if (tid < HDIM + CAND_PER) {
            int c = tid - HDIM;
            edge_sh[c] = NE[(size_t)x_sh * CNEI + myrank * CAND_PER + c];
        }
        __syncthreads();
    }

    // ---------------- output (CTA 0) ----------------
    if (blockIdx.x == 0) {
        int ncache = (L + T) * HDIM;
        for (int i = tid; i < out_size; i += NTHR) {
            float v;
            if (i < ncache) {
                v = cache_s[i >> 6][i & 63];
            } else {
                int tt = i - ncache;
                v = (tt < T) ? (float)tok_s[tt] : 0.0f;
            }
            out[i] = v;
        }
    }
}

extern "C" void kernel_launch(void* const* d_in, const int* in_sizes, int n_in,
                              void* d_out, int out_size) {
    const float* W   = (const float*)d_in[0];
    const float* B   = (const float*)d_in[1];
    const float* POS = (const float*)d_in[2];
    const int*   SE  = (const int*)d_in[3];
    const int*   NE  = (const int*)d_in[4];
    const int*   NN  = (const int*)d_in[5];
    const int*   X0  = (n_in > 6) ? (const int*)d_in[6] : nullptr;
    const int*   MNT = (n_in > 7) ? (const int*)d_in[7] : nullptr;
    int L = in_sizes[3];

    bralm_kernel<<<NBLK, NTHR>>>(W, B, POS, SE, NE, NN, X0, MNT,
                                 (float*)d_out, out_size, L);
}

// round 4
// speedup vs baseline: 3.8558x; 1.3707x over previous
#include <cuda_runtime.h>
#include <cstdint>
#include <stdint.h>
#include <math.h>

#define HDIM   64
#define CNEI   32
#define NBLK   8
#define CAND_PER 4
#define NTHR   512
#define PEROWS 48
#define MAXSEQ 64

__device__ __forceinline__ float gelu_exact(float v) {
    return 0.5f * v * (1.0f + erff(v * 0.70710678118654752440f));
}
__device__ __forceinline__ uint32_t mapa_u32(uint32_t addr, uint32_t rank) {
    uint32_t d;
    asm("mapa.shared::cluster.u32 %0, %1, %2;" : "=r"(d) : "r"(addr), "r"(rank));
    return d;
}
__device__ __forceinline__ void stc_f32(uint32_t addr, float v) {
    asm volatile("st.shared::cluster.f32 [%0], %1;" :: "r"(addr), "f"(v) : "memory");
}
__device__ __forceinline__ float ldc_f32(uint32_t addr) {
    float v;
    asm volatile("ld.shared::cluster.f32 %0, [%1];" : "=f"(v) : "r"(addr) : "memory");
    return v;
}
__device__ __forceinline__ void cluster_sync_all() {
    asm volatile("barrier.cluster.arrive.aligned;" ::: "memory");
    asm volatile("barrier.cluster.wait.aligned;"   ::: "memory");
}

__global__ __launch_bounds__(NTHR, 1) __cluster_dims__(NBLK, 1, 1)
void bralm_kernel(const float* __restrict__ W,    // (E,64,64)
                  const float* __restrict__ Bb,   // (E,1,64)
                  const float* __restrict__ POS,  // (512,1)
                  const int*   __restrict__ SE,   // (L,)
                  const int*   __restrict__ NE,   // (N,32)
                  const int*   __restrict__ NN,   // (N,32)
                  const int*   __restrict__ X0P,
                  const int*   __restrict__ MNTP,
                  float* __restrict__ out,
                  int out_size, int L)
{
    __shared__ float pe_s[PEROWS][HDIM];          // 12 KB
    __shared__ float cache_s[MAXSEQ][HDIM];       // 16 KB
    __shared__ float wts_all[PEROWS][PEROWS];     // 9 KB  (row c = softmax weights for curr=c)
    __shared__ float pos_s[MAXSEQ];
    __shared__ float e_s[HDIM];
    __shared__ float red_s[8][HDIM];              // pooled partials
    __shared__ float4 red4_s[CAND_PER][8][16];    // matvec partials, 8 KB
    __shared__ float dt_s[HDIM / 2];
    __shared__ float nxt_s[2][CAND_PER][HDIM];
    __shared__ float en_all[2][CNEI];
    __shared__ float en_part[8];                  // per-warp energy partials (cand*2+half)
    __shared__ int   nn_s[CNEI];
    __shared__ int   tok_s[PEROWS];
    __shared__ int   edge_sh[CAND_PER];
    __shared__ int   x_sh, idx_sh;

    const int tid = threadIdx.x;
    uint32_t myrank;
    asm("mov.u32 %0, %%cluster_ctarank;" : "=r"(myrank));

    int T = (MNTP != nullptr) ? MNTP[0] : 32;
    if (T < 0) T = 0;
    if (L + T > MAXSEQ) T = MAXSEQ - L;
    if (T > PEROWS)     T = PEROWS;

    // ---- init: div_term, pos, cache zero ----
    if (tid < HDIM / 2)
        dt_s[tid] = (float)pow(10000.0, (double)(2 * tid) / 64.0);
    for (int i = tid; i < MAXSEQ * HDIM; i += NTHR)
        cache_s[i >> 6][i & 63] = 0.0f;
    if (tid < MAXSEQ) pos_s[tid] = POS[tid];
    __syncthreads();

    // pe table (fp32 product, double range-reduce)
    for (int idx = tid; idx < PEROWS * HDIM; idx += NTHR) {
        int i = idx >> 6, h = idx & 63;
        float argf = (float)i * dt_s[h >> 1];
        double ad = (double)argf;
        double kq = rint(ad * 0.15915494309189535);
        double r  = fma(-kq, 6.283185307179586, ad);
        pe_s[i][h] = (h & 1) ? cosf((float)r) : sinf((float)r);
    }

    // precompute ALL softmax weight rows: wts_all[c][j] for j<c, c=1..47
    {
        int w = tid >> 5, lane = tid & 31;
        for (int c = w + 1; c < PEROWS; c += 16) {
            float v0 = (lane      < c) ? pos_s[lane]      : -INFINITY;
            float v1 = (lane + 32 < c) ? pos_s[lane + 32] : -INFINITY;
            float m = fmaxf(v0, v1);
            #pragma unroll
            for (int off = 16; off > 0; off >>= 1)
                m = fmaxf(m, __shfl_xor_sync(0xffffffffu, m, off));
            float u0 = (lane      < c) ? expf(v0 - m) : 0.0f;
            float u1 = (lane + 32 < c) ? expf(v1 - m) : 0.0f;
            float s = u0 + u1;
            #pragma unroll
            for (int off = 16; off > 0; off >>= 1)
                s += __shfl_xor_sync(0xffffffffu, s, off);
            if (lane      < c) wts_all[c][lane]      = u0 / s;
            if (lane + 32 < c) wts_all[c][lane + 32] = u1 / s;
        }
    }
    __syncthreads();

    // ---------------- prompt phase (redundant per CTA) ----------------
    if (tid < HDIM) e_s[tid] = 1.0f / 64.0f;
    __syncthreads();

    for (int i = 0; i < L; ++i) {
        if (i > 0) {
            int p = tid >> 6, kk = tid & 63;
            float acc = 0.0f;
            for (int j = p; j < i; j += 8)
                acc = fmaf(wts_all[i][j], cache_s[j][kk], acc);
            red_s[p][kk] = acc;
            __syncthreads();
            if (tid < HDIM) {
                float a = 0.0f;
                #pragma unroll
                for (int q = 0; q < 8; ++q) a += red_s[q][tid];
                e_s[tid] = a;
            }
            __syncthreads();
        }
        int edge = SE[i];
        if (tid < 128) {   // candidate-0-style float4 matvec
            int hp = tid >> 4, kq = tid & 15;
            const float4* Wb = (const float4*)(W + (size_t)edge * (HDIM * HDIM));
            float4 a4 = make_float4(0.f, 0.f, 0.f, 0.f);
            #pragma unroll
            for (int r = 0; r < 8; ++r) {
                float4 wv = Wb[(hp * 8 + r) * 16 + kq];
                float ev = e_s[hp * 8 + r];
                a4.x = fmaf(ev, wv.x, a4.x); a4.y = fmaf(ev, wv.y, a4.y);
                a4.z = fmaf(ev, wv.z, a4.z); a4.w = fmaf(ev, wv.w, a4.w);
            }
            red4_s[0][hp][kq] = a4;
        }
        __syncthreads();
        if (tid < HDIM) {
            const float* rp = (const float*)&red4_s[0][0][0];
            float v = 0.0f;
            #pragma unroll
            for (int q = 0; q < 8; ++q) v += rp[q * 64 + tid];
            v += Bb[(size_t)edge * HDIM + tid] + pe_s[i][tid];
            cache_s[i][tid] = gelu_exact(v);
        }
        __syncthreads();
    }

    // ---------------- generation phase ----------------
    if (tid == 0) x_sh = (X0P != nullptr) ? X0P[0] : 7;
    __syncthreads();
    if (tid < CAND_PER)
        edge_sh[tid] = NE[(size_t)x_sh * CNEI + myrank * CAND_PER + tid];
    __syncthreads();

    const int g  = tid >> 7;        // candidate 0..3
    const int tc = tid & 127;
    const int hp = tc >> 4;         // 0..7  (8 rows each)
    const int kq = tc & 15;         // 0..15 (float4 column quad)

    for (int t = 0; t < T; ++t) {
        const int curr = L + t;
        const int buf  = t & 1;

        // 1) prefetch: weights (LDG.128), bias, NN row — all overlap pooled-e
        const float4* Wb = (const float4*)(W + (size_t)edge_sh[g] * (HDIM * HDIM));
        float4 wv[8];
        #pragma unroll
        for (int r = 0; r < 8; ++r) wv[r] = Wb[(hp * 8 + r) * 16 + kq];
        float bias_r = 0.0f;
        if (tid < 256) bias_r = Bb[(size_t)edge_sh[tid >> 6] * HDIM + (tid & 63)];
        if (tid < CNEI) nn_s[tid] = NN[(size_t)x_sh * CNEI + tid];

        // 2) pooled e (precomputed weights)
        {
            int p = tid >> 6, kk = tid & 63;
            float acc = 0.0f;
            for (int j = p; j < curr; j += 8)
                acc = fmaf(wts_all[curr][j], cache_s[j][kk], acc);
            red_s[p][kk] = acc;
        }
        __syncthreads();
        if (tid < HDIM) {
            float a = 0.0f;
            #pragma unroll
            for (int q = 0; q < 8; ++q) a += red_s[q][tid];
            e_s[tid] = a;
        }
        __syncthreads();

        // 3) candidate matvec (float4)
        {
            float4 a4 = make_float4(0.f, 0.f, 0.f, 0.f);
            #pragma unroll
            for (int r = 0; r < 8; ++r) {
                float ev = e_s[hp * 8 + r];
                a4.x = fmaf(ev, wv[r].x, a4.x); a4.y = fmaf(ev, wv[r].y, a4.y);
                a4.z = fmaf(ev, wv[r].z, a4.z); a4.w = fmaf(ev, wv[r].w, a4.w);
            }
            red4_s[g][hp][kq] = a4;
        }
        __syncthreads();

        // 4) combine + bias + pe + gelu + fused energy reduce
        if (tid < 256) {
            int cand = tid >> 6, kk = tid & 63;
            const float* rp = (const float*)&red4_s[cand][0][0];
            float v = 0.0f;
            #pragma unroll
            for (int q = 0; q < 8; ++q) v += rp[q * 64 + kk];
            v += bias_r + pe_s[t][kk];
            float ge = gelu_exact(v);
            nxt_s[buf][cand][kk] = ge;
            float sq = ge * ge;
            #pragma unroll
            for (int off = 16; off > 0; off >>= 1)
                sq += __shfl_xor_sync(0xffffffffu, sq, off);
            if ((tid & 31) == 0) en_part[tid >> 5] = sq;  // cand*2 + half
        }
        __syncthreads();

        // 5) energies -> all peer CTAs
        if (tid < 32) {
            int r = tid >> 2, c = tid & 3;
            float en = sqrtf(en_part[2 * c] + en_part[2 * c + 1]);
            uint32_t a = (uint32_t)__cvta_generic_to_shared(&en_all[buf][myrank * CAND_PER + c]);
            stc_f32(mapa_u32(a, (uint32_t)r), en);
        }
        cluster_sync_all();

        // 6) softmax->argmax (warp0)
        if (tid < 32) {
            float en = en_all[buf][tid];
            float m = en;
            #pragma unroll
            for (int off = 16; off > 0; off >>= 1)
                m = fmaxf(m, __shfl_xor_sync(0xffffffffu, m, off));
            float u = expf(en - m);
            float s = u;
            #pragma unroll
            for (int off = 16; off > 0; off >>= 1)
                s += __shfl_xor_sync(0xffffffffu, s, off);
            float p = u / s;
            int bi = tid;
            #pragma unroll
            for (int off = 16; off > 0; off >>= 1) {
                float po = __shfl_xor_sync(0xffffffffu, p, off);
                int   io = __shfl_xor_sync(0xffffffffu, bi, off);
                if (po > p || (po == p && io < bi)) { p = po; bi = io; }
            }
            if (tid == 0) {
                idx_sh = bi;
                int y = nn_s[bi];
                tok_s[t] = y;
                x_sh = y;
            }
        }
        __syncthreads();

        // 7) pull winning vector; fetch next edges
        if (tid < HDIM) {
            int widx = idx_sh >> 2, slot = idx_sh & 3;
            uint32_t a = (uint32_t)__cvta_generic_to_shared(&nxt_s[buf][slot][tid]);
            cache_s[curr][tid] = ldc_f32(mapa_u32(a, (uint32_t)widx));
        } else if (tid < HDIM + CAND_PER) {
            int c = tid - HDIM;
            edge_sh[c] = NE[(size_t)x_sh * CNEI + myrank * CAND_PER + c];
        }
        __syncthreads();
    }

    // ---------------- output (CTA 0) ----------------
    if (blockIdx.x == 0) {
        int ncache = (L + T) * HDIM;
        for (int i = tid; i < out_size; i += NTHR) {
            float v;
            if (i < ncache) v = cache_s[i >> 6][i & 63];
            else {
                int tt = i - ncache;
                v = (tt < T) ? (float)tok_s[tt] : 0.0f;
            }
            out[i] = v;
        }
    }
}

extern "C" void kernel_launch(void* const* d_in, const int* in_sizes, int n_in,
                              void* d_out, int out_size) {
    const float* W   = (const float*)d_in[0];
    const float* B   = (const float*)d_in[1];
    const float* POS = (const float*)d_in[2];
    const int*   SE  = (const int*)d_in[3];
    const int*   NE  = (const int*)d_in[4];
    const int*   NN  = (const int*)d_in[5];
    const int*   X0  = (n_in > 6) ? (const int*)d_in[6] : nullptr;
    const int*   MNT = (n_in > 7) ? (const int*)d_in[7] : nullptr;
    int L = in_sizes[3];

    bralm_kernel<<<NBLK, NTHR>>>(W, B, POS, SE, NE, NN, X0, MNT,
                                 (float*)d_out, out_size, L);
}

// round 5
// speedup vs baseline: 4.3671x; 1.1326x over previous
#include <cuda_runtime.h>
#include <cstdint>
#include <stdint.h>
#include <math.h>

#define HDIM   64
#define CNEI   32
#define NBLK   8
#define CAND_PER 4
#define NTHR   512
#define TROWS  32            // pe rows needed: max(L, T)
#define NROWS  48            // cache rows: L + T
#define WPACK  1128          // packed triangular softmax table: 48*47/2

__device__ __forceinline__ float gelu_exact(float v) {
    return 0.5f * v * (1.0f + erff(v * 0.70710678118654752440f));
}
__device__ __forceinline__ uint32_t mapa_u32(uint32_t addr, uint32_t rank) {
    uint32_t d;
    asm("mapa.shared::cluster.u32 %0, %1, %2;" : "=r"(d) : "r"(addr), "r"(rank));
    return d;
}
__device__ __forceinline__ void stc_f32(uint32_t addr, float v) {
    asm volatile("st.shared::cluster.f32 [%0], %1;" :: "r"(addr), "f"(v) : "memory");
}
__device__ __forceinline__ float ldc_f32(uint32_t addr) {
    float v;
    asm volatile("ld.shared::cluster.f32 %0, [%1];" : "=f"(v) : "r"(addr) : "memory");
    return v;
}
__device__ __forceinline__ void cluster_sync_all() {
    asm volatile("barrier.cluster.arrive.aligned;" ::: "memory");
    asm volatile("barrier.cluster.wait.aligned;"   ::: "memory");
}

__global__ __launch_bounds__(NTHR, 1) __cluster_dims__(NBLK, 1, 1)
void bralm_kernel(const float* __restrict__ W,    // (E,64,64)
                  const float* __restrict__ Bb,   // (E,1,64)
                  const float* __restrict__ POS,  // (512,1)
                  const int*   __restrict__ SE,   // (L,)
                  const int*   __restrict__ NE,   // (N,32)
                  const int*   __restrict__ NN,   // (N,32)
                  const int*   __restrict__ X0P,
                  const int*   __restrict__ MNTP,
                  float* __restrict__ out,
                  int out_size, int L)
{
    __shared__ float pe_s[TROWS][HDIM];          // 8 KB
    __shared__ float cache_s[NROWS][HDIM];       // 12 KB
    __shared__ float wts_p[WPACK];               // 4.5 KB packed: row c at c*(c-1)/2
    __shared__ float pos_s[64];
    __shared__ float e_s[HDIM];
    __shared__ float red_s[4][HDIM];             // pooled partials
    __shared__ float4 red4_s[CAND_PER][8][16];   // matvec partials, 8 KB
    __shared__ float dt_s[HDIM / 2];
    __shared__ float nxt_s[2][CAND_PER][HDIM];   // candidate vectors (local)
    __shared__ float en2_s[2][64];               // 32 cands x 2 half-sums, all ranks
    __shared__ int   ne_br[CNEI][CAND_PER];      // NE rows for all 32 possible branches
    __shared__ int   tok_s[TROWS];
    __shared__ int   edge0[CAND_PER];
    __shared__ int   x_sh, idx_sh;

    const int tid = threadIdx.x;
    uint32_t myrank;
    asm("mov.u32 %0, %%cluster_ctarank;" : "=r"(myrank));

    int T = (MNTP != nullptr) ? MNTP[0] : 32;
    if (T < 0) T = 0;
    if (L + T > NROWS) T = NROWS - L;
    if (T > TROWS)     T = TROWS;

    // ---------------- init ----------------
    if (tid < HDIM / 2)
        dt_s[tid] = (float)pow(10000.0, (double)(2 * tid) / 64.0);
    for (int i = tid; i < NROWS * HDIM; i += NTHR)
        cache_s[i >> 6][i & 63] = 0.0f;
    if (tid < 64) pos_s[tid] = POS[tid];
    __syncthreads();

    for (int idx = tid; idx < TROWS * HDIM; idx += NTHR) {
        int i = idx >> 6, h = idx & 63;
        float argf = (float)i * dt_s[h >> 1];
        double ad = (double)argf;
        double kq = rint(ad * 0.15915494309189535);
        double r  = fma(-kq, 6.283185307179586, ad);
        pe_s[i][h] = (h & 1) ? cosf((float)r) : sinf((float)r);
    }
    // packed softmax rows c = 1..47
    {
        int w = tid >> 5, lane = tid & 31;
        for (int c = w + 1; c < NROWS; c += 16) {
            float v0 = (lane      < c) ? pos_s[lane]      : -INFINITY;
            float v1 = (lane + 32 < c) ? pos_s[lane + 32] : -INFINITY;
            float m = fmaxf(v0, v1);
            #pragma unroll
            for (int off = 16; off > 0; off >>= 1)
                m = fmaxf(m, __shfl_xor_sync(0xffffffffu, m, off));
            float u0 = (lane      < c) ? expf(v0 - m) : 0.0f;
            float u1 = (lane + 32 < c) ? expf(v1 - m) : 0.0f;
            float s = u0 + u1;
            #pragma unroll
            for (int off = 16; off > 0; off >>= 1)
                s += __shfl_xor_sync(0xffffffffu, s, off);
            int base = c * (c - 1) / 2;
            if (lane      < c) wts_p[base + lane]      = u0 / s;
            if (lane + 32 < c) wts_p[base + lane + 32] = u1 / s;
        }
    }
    __syncthreads();

    // ---------------- prompt phase (redundant per CTA) ----------------
    if (tid < HDIM) e_s[tid] = 1.0f / 64.0f;
    __syncthreads();

    for (int i = 0; i < L; ++i) {
        int edge = SE[i];
        // prefetch weights + bias, overlapping pooled-e
        float4 wvp[8];
        if (tid < 128) {
            int hp = tid >> 4, kq = tid & 15;
            const float4* Wb = (const float4*)(W + (size_t)edge * (HDIM * HDIM));
            #pragma unroll
            for (int r = 0; r < 8; ++r) wvp[r] = Wb[(hp * 8 + r) * 16 + kq];
        }
        float bias_p = 0.0f;
        if (tid < 64) bias_p = Bb[(size_t)edge * HDIM + tid];

        if (i > 0) {
            int base = i * (i - 1) / 2;
            if (tid < 256) {
                int p = tid >> 6, k = tid & 63;
                float acc = 0.0f;
                for (int j = p; j < i; j += 4)
                    acc = fmaf(wts_p[base + j], cache_s[j][k], acc);
                red_s[p][k] = acc;
            }
            __syncthreads();
            if (tid < HDIM)
                e_s[tid] = red_s[0][tid] + red_s[1][tid] + red_s[2][tid] + red_s[3][tid];
            __syncthreads();
        }
        if (tid < 128) {
            int hp = tid >> 4, kq = tid & 15;
            float4 a4 = make_float4(0.f, 0.f, 0.f, 0.f);
            #pragma unroll
            for (int r = 0; r < 8; ++r) {
                float ev = e_s[hp * 8 + r];
                a4.x = fmaf(ev, wvp[r].x, a4.x); a4.y = fmaf(ev, wvp[r].y, a4.y);
                a4.z = fmaf(ev, wvp[r].z, a4.z); a4.w = fmaf(ev, wvp[r].w, a4.w);
            }
            red4_s[0][hp][kq] = a4;
        }
        __syncthreads();
        if (tid < HDIM) {
            const float* rp = (const float*)&red4_s[0][0][0];
            float v = 0.0f;
            #pragma unroll
            for (int q = 0; q < 8; ++q) v += rp[q * 64 + tid];
            v += bias_p + pe_s[i][tid];
            cache_s[i][tid] = gelu_exact(v);
        }
        __syncthreads();
    }

    // ---------------- generation: priming ----------------
    if (tid == 0) x_sh = (X0P != nullptr) ? X0P[0] : 7;
    __syncthreads();
    const int x0v = x_sh;

    int nn_reg = 0, nn_next = 0;
    int ne_c0 = 0, ne_c1 = 0, ne_c2 = 0, ne_c3 = 0;
    if (tid < 32) {
        nn_reg = NN[(size_t)x0v * CNEI + tid];               // branch tokens for step 0
        ne_br[tid][0] = NE[(size_t)nn_reg * CNEI + myrank * 4 + 0];
        ne_br[tid][1] = NE[(size_t)nn_reg * CNEI + myrank * 4 + 1];
        ne_br[tid][2] = NE[(size_t)nn_reg * CNEI + myrank * 4 + 2];
        ne_br[tid][3] = NE[(size_t)nn_reg * CNEI + myrank * 4 + 3];
    }
    if (tid < CAND_PER) edge0[tid] = NE[(size_t)x0v * CNEI + myrank * 4 + tid];
    __syncthreads();

    const int g  = tid >> 7;       // candidate 0..3
    const int tc = tid & 127;
    const int hp = tc >> 4;        // 0..7
    const int kq = tc & 15;        // 0..15

    // weights + bias for step 0
    float4 wv[8];
    {
        const float4* Wb = (const float4*)(W + (size_t)edge0[g] * (HDIM * HDIM));
        #pragma unroll
        for (int r = 0; r < 8; ++r) wv[r] = Wb[(hp * 8 + r) * 16 + kq];
    }
    float bias_r = 0.0f;
    if (tid < 256) bias_r = Bb[(size_t)edge0[tid >> 6] * HDIM + (tid & 63)];

    // e for curr = L
    {
        int base = L * (L - 1) / 2;
        if (tid < 256) {
            int p = tid >> 6, k = tid & 63;
            float acc = 0.0f;
            for (int j = p; j < L; j += 4)
                acc = fmaf(wts_p[base + j], cache_s[j][k], acc);
            red_s[p][k] = acc;
        }
        __syncthreads();
        if (tid < HDIM)
            e_s[tid] = red_s[0][tid] + red_s[1][tid] + red_s[2][tid] + red_s[3][tid];
        __syncthreads();
    }

    // ---------------- generation loop ----------------
    for (int t = 0; t < T; ++t) {
        const int curr = L + t;
        const int cb   = t & 1;

        // 1) matvec partials
        {
            float4 a4 = make_float4(0.f, 0.f, 0.f, 0.f);
            #pragma unroll
            for (int r = 0; r < 8; ++r) {
                float ev = e_s[hp * 8 + r];
                a4.x = fmaf(ev, wv[r].x, a4.x); a4.y = fmaf(ev, wv[r].y, a4.y);
                a4.z = fmaf(ev, wv[r].z, a4.z); a4.w = fmaf(ev, wv[r].w, a4.w);
            }
            red4_s[g][hp][kq] = a4;
        }
        __syncthreads();   // bar1

        // 2) combine + gelu + distributed energy push  |  partial pooled-e
        if (tid < 256) {
            // warp0: consume nn_next, issue NE branch gathers (off critical path)
            if (tid < 32 && t > 0) {
                nn_reg = nn_next;
                ne_c0 = NE[(size_t)nn_reg * CNEI + myrank * 4 + 0];
                ne_c1 = NE[(size_t)nn_reg * CNEI + myrank * 4 + 1];
                ne_c2 = NE[(size_t)nn_reg * CNEI + myrank * 4 + 2];
                ne_c3 = NE[(size_t)nn_reg * CNEI + myrank * 4 + 3];
            }
            int cand = tid >> 6, kk = tid & 63;
            const float* rp = (const float*)&red4_s[cand][0][0];
            float v = 0.0f;
            #pragma unroll
            for (int q = 0; q < 8; ++q) v += rp[q * 64 + kk];
            v += bias_r + pe_s[t][kk];
            float ge = gelu_exact(v);
            nxt_s[cb][cand][kk] = ge;
            float sq = ge * ge;
            #pragma unroll
            for (int off = 16; off > 0; off >>= 1)
                sq += __shfl_xor_sync(0xffffffffu, sq, off);
            // push this warp's half-sum to all 8 ranks
            int w = tid >> 5, lane = tid & 31;
            if (lane < NBLK) {
                uint32_t a = (uint32_t)__cvta_generic_to_shared(&en2_s[cb][myrank * 8 + w]);
                stc_f32(mapa_u32(a, (uint32_t)lane), sq);
            }
        } else if (t + 1 < T) {
            // partial pooled-e for step t+1 over rows j < curr
            int p = (tid >> 6) - 4, k = tid & 63;
            int base1 = (curr + 1) * curr / 2;
            float acc = 0.0f;
            for (int j = p; j < curr; j += 4)
                acc = fmaf(wts_p[base1 + j], cache_s[j][k], acc);
            red_s[p][k] = acc;
        }

        cluster_sync_all();

        // 4) argmax (warp0, redundant per CTA) + branch STS + NN prefetch
        if (tid < 32) {
            int r = tid >> 2, cl = tid & 3;
            float en = sqrtf(en2_s[cb][r * 8 + cl * 2] + en2_s[cb][r * 8 + cl * 2 + 1]);
            float m = en;
            #pragma unroll
            for (int off = 16; off > 0; off >>= 1)
                m = fmaxf(m, __shfl_xor_sync(0xffffffffu, m, off));
            float u = expf(en - m);
            float s = u;
            #pragma unroll
            for (int off = 16; off > 0; off >>= 1)
                s += __shfl_xor_sync(0xffffffffu, s, off);
            float p = u / s;
            int bi = tid;
            #pragma unroll
            for (int off = 16; off > 0; off >>= 1) {
                float po = __shfl_xor_sync(0xffffffffu, p, off);
                int   io = __shfl_xor_sync(0xffffffffu, bi, off);
                if (po > p || (po == p && io < bi)) { p = po; bi = io; }
            }
            int y = __shfl_sync(0xffffffffu, nn_reg, bi);    // winning token
            if (tid == 0) { idx_sh = bi; tok_s[t] = y; }
            if (t > 0) {   // publish NE rows gathered last region-2 (data long ready)
                ne_br[tid][0] = ne_c0; ne_br[tid][1] = ne_c1;
                ne_br[tid][2] = ne_c2; ne_br[tid][3] = ne_c3;
            }
            nn_next = NN[(size_t)y * CNEI + tid];            // issue, consume next step
        }
        __syncthreads();   // bar3

        // 5) next-step loads + winner pull + e update
        const int eidx = idx_sh;
        {
            int edge_g = ne_br[eidx][g];
            const float4* Wb = (const float4*)(W + (size_t)edge_g * (HDIM * HDIM));
            #pragma unroll
            for (int r = 0; r < 8; ++r) wv[r] = Wb[(hp * 8 + r) * 16 + kq];
        }
        if (tid < 256)
            bias_r = Bb[(size_t)ne_br[eidx][tid >> 6] * HDIM + (tid & 63)];
        if (tid < HDIM) {
            int wr = eidx >> 2, slot = eidx & 3;
            uint32_t a = (uint32_t)__cvta_generic_to_shared(&nxt_s[cb][slot][tid]);
            float win = ldc_f32(mapa_u32(a, (uint32_t)wr));
            cache_s[curr][tid] = win;
            if (t + 1 < T) {
                int base1 = (curr + 1) * curr / 2;
                float ee = red_s[0][tid] + red_s[1][tid] + red_s[2][tid] + red_s[3][tid];
                e_s[tid] = fmaf(wts_p[base1 + curr], win, ee);
            }
        }
        __syncthreads();   // bar4
    }

    // ---------------- output (CTA 0) ----------------
    if (blockIdx.x == 0) {
        int ncache = (L + T) * HDIM;
        for (int i = tid; i < out_size; i += NTHR) {
            float v;
            if (i < ncache) v = cache_s[i >> 6][i & 63];
            else {
                int tt = i - ncache;
                v = (tt < T) ? (float)tok_s[tt] : 0.0f;
            }
            out[i] = v;
        }
    }
}

extern "C" void kernel_launch(void* const* d_in, const int* in_sizes, int n_in,
                              void* d_out, int out_size) {
    const float* W   = (const float*)d_in[0];
    const float* B   = (const float*)d_in[1];
    const float* POS = (const float*)d_in[2];
    const int*   SE  = (const int*)d_in[3];
    const int*   NE  = (const int*)d_in[4];
    const int*   NN  = (const int*)d_in[5];
    const int*   X0  = (n_in > 6) ? (const int*)d_in[6] : nullptr;
    const int*   MNT = (n_in > 7) ? (const int*)d_in[7] : nullptr;
    int L = in_sizes[3];

    bralm_kernel<<<NBLK, NTHR>>>(W, B, POS, SE, NE, NN, X0, MNT,
                                 (float*)d_out, out_size, L);
}

// round 6
// speedup vs baseline: 4.5707x; 1.0466x over previous
#include <cuda_runtime.h>
#include <cstdint>
#include <stdint.h>
#include <math.h>

#define HDIM   64
#define CNEI   32
#define NBLK   8
#define NTHR   1024
#define TROWS  32
#define NROWS  48
#define WPACK  1128   // 48*47/2 packed triangular softmax table

__device__ __forceinline__ float gelu_exact(float v) {
    return 0.5f * v * (1.0f + erff(v * 0.70710678118654752440f));
}
__device__ __forceinline__ uint32_t mapa_u32(uint32_t addr, uint32_t rank) {
    uint32_t d;
    asm("mapa.shared::cluster.u32 %0, %1, %2;" : "=r"(d) : "r"(addr), "r"(rank));
    return d;
}
__device__ __forceinline__ void stc_f32(uint32_t addr, float v) {
    asm volatile("st.shared::cluster.f32 [%0], %1;" :: "r"(addr), "f"(v) : "memory");
}
__device__ __forceinline__ float ldc_f32(uint32_t addr) {
    float v;
    asm volatile("ld.shared::cluster.f32 %0, [%1];" : "=f"(v) : "r"(addr) : "memory");
    return v;
}
__device__ __forceinline__ void cluster_sync_all() {
    asm volatile("barrier.cluster.arrive.aligned;" ::: "memory");
    asm volatile("barrier.cluster.wait.aligned;"   ::: "memory");
}

__global__ __launch_bounds__(NTHR, 1) __cluster_dims__(NBLK, 1, 1)
void bralm_kernel(const float* __restrict__ W,
                  const float* __restrict__ Bb,
                  const float* __restrict__ POS,
                  const int*   __restrict__ SE,
                  const int*   __restrict__ NE,
                  const int*   __restrict__ NN,
                  const int*   __restrict__ X0P,
                  const int*   __restrict__ MNTP,
                  float* __restrict__ out,
                  int out_size, int L)
{
    __shared__ float pe_s[TROWS][HDIM];       // 8 KB
    __shared__ float cache_s[NROWS][HDIM];    // 12 KB
    __shared__ float wts_p[WPACK];            // 4.5 KB
    __shared__ float pos_s[64];
    __shared__ float e_s[HDIM];
    __shared__ float red_s[8][HDIM];          // pooled partials, 2 KB
    __shared__ float red_f[4][8][HDIM];       // matvec partials, 8 KB
    __shared__ float dt_s[HDIM / 2];
    __shared__ float nxt_s[2][4][HDIM];       // 2 KB
    __shared__ float en2_s[2][64];
    __shared__ int   ne_br[CNEI][4];
    __shared__ int   tok_s[TROWS];
    __shared__ int   edge0[4];
    __shared__ int   x_sh, idx_sh;

    const int tid = threadIdx.x;
    uint32_t myrank;
    asm("mov.u32 %0, %%cluster_ctarank;" : "=r"(myrank));

    int T = (MNTP != nullptr) ? MNTP[0] : 32;
    if (T < 0) T = 0;
    if (L + T > NROWS) T = NROWS - L;
    if (T > TROWS)     T = TROWS;

    // ---------------- init ----------------
    if (tid < HDIM / 2)
        dt_s[tid] = (float)pow(10000.0, (double)(2 * tid) / 64.0);
    for (int i = tid; i < NROWS * HDIM; i += NTHR)
        cache_s[i >> 6][i & 63] = 0.0f;
    if (tid < 64) pos_s[tid] = POS[tid];
    __syncthreads();

    for (int idx = tid; idx < TROWS * HDIM; idx += NTHR) {
        int i = idx >> 6, h = idx & 63;
        float argf = (float)i * dt_s[h >> 1];
        double ad = (double)argf;
        double kq2 = rint(ad * 0.15915494309189535);
        double r   = fma(-kq2, 6.283185307179586, ad);
        pe_s[i][h] = (h & 1) ? cosf((float)r) : sinf((float)r);
    }
    {   // packed softmax rows c = 1..47
        int w = tid >> 5, lane = tid & 31;
        for (int c = w + 1; c < NROWS; c += 32) {
            float v0 = (lane      < c) ? pos_s[lane]      : -INFINITY;
            float v1 = (lane + 32 < c) ? pos_s[lane + 32] : -INFINITY;
            float m = fmaxf(v0, v1);
            #pragma unroll
            for (int off = 16; off > 0; off >>= 1)
                m = fmaxf(m, __shfl_xor_sync(0xffffffffu, m, off));
            float u0 = (lane      < c) ? expf(v0 - m) : 0.0f;
            float u1 = (lane + 32 < c) ? expf(v1 - m) : 0.0f;
            float s = u0 + u1;
            #pragma unroll
            for (int off = 16; off > 0; off >>= 1)
                s += __shfl_xor_sync(0xffffffffu, s, off);
            int base = c * (c - 1) / 2;
            if (lane      < c) wts_p[base + lane]      = u0 / s;
            if (lane + 32 < c) wts_p[base + lane + 32] = u1 / s;
        }
    }
    __syncthreads();

    // thread roles (matvec): candidate g, 4 rows x float4 cols
    const int g   = tid >> 8;        // 0..3
    const int tc  = tid & 255;
    const int hp  = tc >> 4;         // 0..15 -> rows hp*4..hp*4+3
    const int kq  = tc & 15;         // float4 col quad
    const int w2  = tc >> 5;         // warp within group, 0..7
    const int lane = tid & 31;

    // ---------------- prompt (redundant per CTA; 256 threads matvec) ----------------
    if (tid < HDIM) e_s[tid] = 1.0f / 64.0f;
    __syncthreads();

    for (int i = 0; i < L; ++i) {
        int edge = SE[i];
        float4 wvp[4];
        if (tid < 256) {
            const float4* Wb = (const float4*)(W + (size_t)edge * (HDIM * HDIM));
            #pragma unroll
            for (int r = 0; r < 4; ++r) wvp[r] = Wb[(hp * 4 + r) * 16 + kq];
        }
        float bias_p = 0.0f;
        if (tid < 64) bias_p = Bb[(size_t)edge * HDIM + tid];

        if (i > 0) {
            int base = i * (i - 1) / 2;
            if (tid >= 512) {
                int p = (tid >> 6) - 8, k = tid & 63;
                float acc = 0.0f;
                for (int j = p; j < i; j += 8)
                    acc = fmaf(wts_p[base + j], cache_s[j][k], acc);
                red_s[p][k] = acc;
            }
            __syncthreads();
            if (tid < HDIM) {
                float a = 0.0f;
                #pragma unroll
                for (int q = 0; q < 8; ++q) a += red_s[q][tid];
                e_s[tid] = a;
            }
            __syncthreads();
        }
        if (tid < 256) {
            float4 a4 = make_float4(0.f, 0.f, 0.f, 0.f);
            #pragma unroll
            for (int r = 0; r < 4; ++r) {
                float ev = e_s[hp * 4 + r];
                a4.x = fmaf(ev, wvp[r].x, a4.x); a4.y = fmaf(ev, wvp[r].y, a4.y);
                a4.z = fmaf(ev, wvp[r].z, a4.z); a4.w = fmaf(ev, wvp[r].w, a4.w);
            }
            // fold hp pairs (lanes ^16) -> 8 partials
            a4.x += __shfl_xor_sync(0xffffffffu, a4.x, 16);
            a4.y += __shfl_xor_sync(0xffffffffu, a4.y, 16);
            a4.z += __shfl_xor_sync(0xffffffffu, a4.z, 16);
            a4.w += __shfl_xor_sync(0xffffffffu, a4.w, 16);
            if ((tc & 16) == 0)
                *(float4*)&red_f[0][w2][kq * 4] = a4;
        }
        __syncthreads();
        if (tid < HDIM) {
            float v = 0.0f;
            #pragma unroll
            for (int q = 0; q < 8; ++q) v += red_f[0][q][tid];
            v += bias_p + pe_s[i][tid];
            cache_s[i][tid] = gelu_exact(v);
        }
        __syncthreads();
    }

    // ---------------- generation priming ----------------
    if (tid == 0) x_sh = (X0P != nullptr) ? X0P[0] : 7;
    __syncthreads();
    const int x0v = x_sh;

    int nn_reg = 0, nn_next = 0;
    int ne_c0 = 0, ne_c1 = 0, ne_c2 = 0, ne_c3 = 0;
    if (tid < 32) {
        nn_reg = NN[(size_t)x0v * CNEI + tid];
        ne_br[tid][0] = NE[(size_t)nn_reg * CNEI + myrank * 4 + 0];
        ne_br[tid][1] = NE[(size_t)nn_reg * CNEI + myrank * 4 + 1];
        ne_br[tid][2] = NE[(size_t)nn_reg * CNEI + myrank * 4 + 2];
        ne_br[tid][3] = NE[(size_t)nn_reg * CNEI + myrank * 4 + 3];
    }
    if (tid < 4) edge0[tid] = NE[(size_t)x0v * CNEI + myrank * 4 + tid];
    __syncthreads();

    float4 wv[4];
    {
        const float4* Wb = (const float4*)(W + (size_t)edge0[g] * (HDIM * HDIM));
        #pragma unroll
        for (int r = 0; r < 4; ++r) wv[r] = Wb[(hp * 4 + r) * 16 + kq];
    }
    float bias_r = 0.0f;
    if (tid < 256) bias_r = Bb[(size_t)edge0[tid >> 6] * HDIM + (tid & 63)];

    {   // e for curr = L
        int base = L * (L - 1) / 2;
        if (tid >= 512) {
            int p = (tid >> 6) - 8, k = tid & 63;
            float acc = 0.0f;
            for (int j = p; j < L; j += 8)
                acc = fmaf(wts_p[base + j], cache_s[j][k], acc);
            red_s[p][k] = acc;
        }
        __syncthreads();
        if (tid < HDIM) {
            float a = 0.0f;
            #pragma unroll
            for (int q = 0; q < 8; ++q) a += red_s[q][tid];
            e_s[tid] = a;
        }
        __syncthreads();
    }

    // ---------------- generation loop ----------------
    for (int t = 0; t < T; ++t) {
        const int curr = L + t;
        const int cb   = t & 1;

        // 1) matvec partials (all 1024 threads)
        {
            float4 a4 = make_float4(0.f, 0.f, 0.f, 0.f);
            #pragma unroll
            for (int r = 0; r < 4; ++r) {
                float ev = e_s[hp * 4 + r];
                a4.x = fmaf(ev, wv[r].x, a4.x); a4.y = fmaf(ev, wv[r].y, a4.y);
                a4.z = fmaf(ev, wv[r].z, a4.z); a4.w = fmaf(ev, wv[r].w, a4.w);
            }
            a4.x += __shfl_xor_sync(0xffffffffu, a4.x, 16);
            a4.y += __shfl_xor_sync(0xffffffffu, a4.y, 16);
            a4.z += __shfl_xor_sync(0xffffffffu, a4.z, 16);
            a4.w += __shfl_xor_sync(0xffffffffu, a4.w, 16);
            if ((tc & 16) == 0)
                *(float4*)&red_f[g][w2][kq * 4] = a4;
        }
        __syncthreads();   // bar1

        // 2) combine+gelu+energy push (tid<256) | NE gathers (warp0) | pooled partials (tid>=512)
        if (tid < 256) {
            if (tid < 32 && t > 0) {
                nn_reg = nn_next;
                ne_c0 = NE[(size_t)nn_reg * CNEI + myrank * 4 + 0];
                ne_c1 = NE[(size_t)nn_reg * CNEI + myrank * 4 + 1];
                ne_c2 = NE[(size_t)nn_reg * CNEI + myrank * 4 + 2];
                ne_c3 = NE[(size_t)nn_reg * CNEI + myrank * 4 + 3];
            }
            int cand = tid >> 6, kk = tid & 63;
            float v = 0.0f;
            #pragma unroll
            for (int q = 0; q < 8; ++q) v += red_f[cand][q][kk];
            v += bias_r + pe_s[t][kk];
            float ge = gelu_exact(v);
            nxt_s[cb][cand][kk] = ge;
            float sq = ge * ge;
            #pragma unroll
            for (int off = 16; off > 0; off >>= 1)
                sq += __shfl_xor_sync(0xffffffffu, sq, off);
            int w = tid >> 5;
            if (lane < NBLK) {
                uint32_t a = (uint32_t)__cvta_generic_to_shared(&en2_s[cb][myrank * 8 + w]);
                stc_f32(mapa_u32(a, (uint32_t)lane), sq);
            }
        } else if (tid >= 512 && t + 1 < T) {
            int p = (tid >> 6) - 8, k = tid & 63;
            int base1 = (curr + 1) * curr / 2;
            float acc = 0.0f;
            for (int j = p; j < curr; j += 8)
                acc = fmaf(wts_p[base1 + j], cache_s[j][k], acc);
            red_s[p][k] = acc;
        }

        cluster_sync_all();

        // 3) argmax on raw sum-of-squares (monotonic: == argmax(softmax(norm)))
        if (tid < 32) {
            int r = tid >> 2, cl = tid & 3;
            float en = en2_s[cb][r * 8 + cl * 2] + en2_s[cb][r * 8 + cl * 2 + 1];
            float best = en; int bi = tid;
            #pragma unroll
            for (int off = 16; off > 0; off >>= 1) {
                float bo = __shfl_xor_sync(0xffffffffu, best, off);
                int   io = __shfl_xor_sync(0xffffffffu, bi, off);
                if (bo > best || (bo == best && io < bi)) { best = bo; bi = io; }
            }
            int y = __shfl_sync(0xffffffffu, nn_reg, bi);
            if (tid == 0) { idx_sh = bi; tok_s[t] = y; }
            if (t > 0) {
                ne_br[tid][0] = ne_c0; ne_br[tid][1] = ne_c1;
                ne_br[tid][2] = ne_c2; ne_br[tid][3] = ne_c3;
            }
            nn_next = NN[(size_t)y * CNEI + tid];
        }
        __syncthreads();   // bar3

        // 4) next-step weight/bias loads + winner pull + e update
        const int eidx = idx_sh;
        {
            int edge_g = ne_br[eidx][g];
            const float4* Wb = (const float4*)(W + (size_t)edge_g * (HDIM * HDIM));
            #pragma unroll
            for (int r = 0; r < 4; ++r) wv[r] = Wb[(hp * 4 + r) * 16 + kq];
        }
        if (tid < 256)
            bias_r = Bb[(size_t)ne_br[eidx][tid >> 6] * HDIM + (tid & 63)];
        if (tid < HDIM) {
            int wr = eidx >> 2, slot = eidx & 3;
            uint32_t a = (uint32_t)__cvta_generic_to_shared(&nxt_s[cb][slot][tid]);
            float win = ldc_f32(mapa_u32(a, (uint32_t)wr));
            cache_s[curr][tid] = win;
            if (t + 1 < T) {
                int base1 = (curr + 1) * curr / 2;
                float ee = 0.0f;
                #pragma unroll
                for (int q = 0; q < 8; ++q) ee += red_s[q][tid];
                e_s[tid] = fmaf(wts_p[base1 + curr], win, ee);
            }
        }
        __syncthreads();   // bar4
    }

    // ---------------- output (CTA 0) ----------------
    if (blockIdx.x == 0) {
        int ncache = (L + T) * HDIM;
        for (int i = tid; i < out_size; i += NTHR) {
            float v;
            if (i < ncache) v = cache_s[i >> 6][i & 63];
            else {
                int tt = i - ncache;
                v = (tt < T) ? (float)tok_s[tt] : 0.0f;
            }
            out[i] = v;
        }
    }
}

extern "C" void kernel_launch(void* const* d_in, const int* in_sizes, int n_in,
                              void* d_out, int out_size) {
    const float* W   = (const float*)d_in[0];
    const float* B   = (const float*)d_in[1];
    const float* POS = (const float*)d_in[2];
    const int*   SE  = (const int*)d_in[3];
    const int*   NE  = (const int*)d_in[4];
    const int*   NN  = (const int*)d_in[5];
    const int*   X0  = (n_in > 6) ? (const int*)d_in[6] : nullptr;
    const int*   MNT = (n_in > 7) ? (const int*)d_in[7] : nullptr;
    int L = in_sizes[3];

    bralm_kernel<<<NBLK, NTHR>>>(W, B, POS, SE, NE, NN, X0, MNT,
                                 (float*)d_out, out_size, L);
}

// round 7
// speedup vs baseline: 5.0206x; 1.0985x over previous
#include <cuda_runtime.h>
#include <cstdint>
#include <stdint.h>
#include <math.h>

#define HDIM   64
#define CNEI   32
#define NBLK   8
#define NTHR   1024
#define TROWS  32
#define NROWS  48
#define WPACK  1128

struct __align__(16) PushBlk { float vec[4][HDIM]; float en[8]; };  // 1056 B
#define PUSH_BYTES 1056
#define EXPECT_TX ((NBLK - 1) * PUSH_BYTES)

struct __align__(16) Smem {
    PushBlk rx[2][NBLK];              // 16896 B
    float pe[TROWS][HDIM];            // 8 KB
    float cache[NROWS][HDIM];         // 12 KB
    float wts[WPACK];                 // 4.5 KB
    float red_s[8][HDIM];             // 2 KB
    float red_f[4][8][HDIM];          // 8 KB
    float pos[64];
    float dt[32];
    int   tok[TROWS];
    int   ne_br[CNEI][4];
    int   edge0[4];
    int   x0;
    unsigned long long mbar[2];
};

__device__ __forceinline__ float gelu_exact(float v) {
    return 0.5f * v * (1.0f + erff(v * 0.70710678118654752440f));
}
__device__ __forceinline__ uint32_t mapa_u32(uint32_t addr, uint32_t rank) {
    uint32_t d;
    asm("mapa.shared::cluster.u32 %0, %1, %2;" : "=r"(d) : "r"(addr), "r"(rank));
    return d;
}
__device__ __forceinline__ void cluster_sync_all() {
    asm volatile("barrier.cluster.arrive.aligned;" ::: "memory");
    asm volatile("barrier.cluster.wait.aligned;"   ::: "memory");
}
__device__ __forceinline__ void mbar_init(uint32_t a, uint32_t cnt) {
    asm volatile("mbarrier.init.shared.b64 [%0], %1;" :: "r"(a), "r"(cnt) : "memory");
}
__device__ __forceinline__ void mbar_arrive_expect(uint32_t a, uint32_t tx) {
    asm volatile("mbarrier.arrive.expect_tx.shared.b64 _, [%0], %1;" :: "r"(a), "r"(tx) : "memory");
}
__device__ __forceinline__ void mbar_wait(uint32_t a, uint32_t parity) {
    uint32_t done;
    asm volatile(
        "{\n\t.reg .pred p;\n\t"
        "mbarrier.try_wait.parity.acquire.cta.shared::cta.b64 p, [%1], %2;\n\t"
        "selp.b32 %0, 1, 0, p;\n\t}"
        : "=r"(done) : "r"(a), "r"(parity) : "memory");
    if (!done) {
        asm volatile(
            "{\n\t.reg .pred P1;\n\t"
            "WAIT_LOOP_%=:\n\t"
            "mbarrier.try_wait.parity.acquire.cta.shared::cta.b64 P1, [%0], %1, 0x989680;\n\t"
            "@P1 bra.uni WAIT_DONE_%=;\n\t"
            "bra.uni WAIT_LOOP_%=;\n\t"
            "WAIT_DONE_%=:\n\t}"
            :: "r"(a), "r"(parity) : "memory");
    }
}
__device__ __forceinline__ void bulk_s2s(uint32_t dst, uint32_t src, uint32_t bytes, uint32_t rmbar) {
    asm volatile(
        "cp.async.bulk.shared::cluster.shared::cta.mbarrier::complete_tx::bytes [%0], [%1], %2, [%3];"
        :: "r"(dst), "r"(src), "r"(bytes), "r"(rmbar) : "memory");
}

__global__ __launch_bounds__(NTHR, 1) __cluster_dims__(NBLK, 1, 1)
void bralm_kernel(const float* __restrict__ W,
                  const float* __restrict__ Bb,
                  const float* __restrict__ POS,
                  const int*   __restrict__ SE,
                  const int*   __restrict__ NE,
                  const int*   __restrict__ NN,
                  const int*   __restrict__ X0P,
                  const int*   __restrict__ MNTP,
                  float* __restrict__ out,
                  int out_size, int L)
{
    extern __shared__ __align__(16) char smem_raw[];
    Smem* S = (Smem*)smem_raw;

    const int tid  = threadIdx.x;
    const int lane = tid & 31;
    uint32_t myrank;
    asm("mov.u32 %0, %%cluster_ctarank;" : "=r"(myrank));

    const uint32_t mbar_a0 = (uint32_t)__cvta_generic_to_shared(&S->mbar[0]);
    const uint32_t mbar_a1 = (uint32_t)__cvta_generic_to_shared(&S->mbar[1]);

    int T = (MNTP != nullptr) ? MNTP[0] : 32;
    if (T < 0) T = 0;
    if (L + T > NROWS) T = NROWS - L;
    if (T > TROWS)     T = TROWS;

    // ---------------- init ----------------
    if (tid == 0) { mbar_init(mbar_a0, 1); mbar_init(mbar_a1, 1); }
    if (tid < HDIM / 2)
        S->dt[tid] = (float)pow(10000.0, (double)(2 * tid) / 64.0);
    for (int i = tid; i < NROWS * HDIM; i += NTHR)
        S->cache[i >> 6][i & 63] = 0.0f;
    if (tid < 64) S->pos[tid] = POS[tid];
    __syncthreads();

    for (int idx = tid; idx < TROWS * HDIM; idx += NTHR) {
        int i = idx >> 6, h = idx & 63;
        float argf = (float)i * S->dt[h >> 1];
        double ad = (double)argf;
        double kq2 = rint(ad * 0.15915494309189535);
        double r   = fma(-kq2, 6.283185307179586, ad);
        S->pe[i][h] = (h & 1) ? cosf((float)r) : sinf((float)r);
    }
    {   // packed softmax rows c = 1..47
        int w = tid >> 5;
        for (int c = w + 1; c < NROWS; c += 32) {
            float v0 = (lane      < c) ? S->pos[lane]      : -INFINITY;
            float v1 = (lane + 32 < c) ? S->pos[lane + 32] : -INFINITY;
            float m = fmaxf(v0, v1);
            #pragma unroll
            for (int off = 16; off > 0; off >>= 1)
                m = fmaxf(m, __shfl_xor_sync(0xffffffffu, m, off));
            float u0 = (lane      < c) ? expf(v0 - m) : 0.0f;
            float u1 = (lane + 32 < c) ? expf(v1 - m) : 0.0f;
            float s = u0 + u1;
            #pragma unroll
            for (int off = 16; off > 0; off >>= 1)
                s += __shfl_xor_sync(0xffffffffu, s, off);
            int base = c * (c - 1) / 2;
            if (lane      < c) S->wts[base + lane]      = u0 / s;
            if (lane + 32 < c) S->wts[base + lane + 32] = u1 / s;
        }
    }
    __syncthreads();

    // thread roles: candidate g, rows hp*4.., float4 col quad kq
    const int g   = tid >> 8;
    const int tc  = tid & 255;
    const int hp  = tc >> 4;
    const int kq  = tc & 15;
    const int w2  = tc >> 5;

    // ---------------- prompt (redundant per CTA) ----------------
    // e_s lives in red_s[0] row? use a dedicated spot: reuse rx[0][0].vec[0] as e_s
    float* e_s = &S->rx[0][0].vec[0][0];   // safe: rx not used until gen loop... NOT safe (step0 cb=0, myrank0 writes vec). Use separate:
    // use S->red_f[3][7] row as e-vector storage would alias; instead use a static small array:
    __shared__ float e_vec[HDIM];
    e_s = e_vec;

    if (tid < HDIM) e_s[tid] = 1.0f / 64.0f;
    __syncthreads();

    for (int i = 0; i < L; ++i) {
        int edge = SE[i];
        float4 wvp[4];
        if (tid < 256) {
            const float4* Wb = (const float4*)(W + (size_t)edge * (HDIM * HDIM));
            #pragma unroll
            for (int r = 0; r < 4; ++r) wvp[r] = Wb[(hp * 4 + r) * 16 + kq];
        }
        float bias_p = 0.0f;
        if (tid < 64) bias_p = Bb[(size_t)edge * HDIM + tid];

        if (i > 0) {
            int base = i * (i - 1) / 2;
            if (tid >= 512) {
                int p = (tid >> 6) - 8, k = tid & 63;
                float acc = 0.0f;
                for (int j = p; j < i; j += 8)
                    acc = fmaf(S->wts[base + j], S->cache[j][k], acc);
                S->red_s[p][k] = acc;
            }
            __syncthreads();
            if (tid < HDIM) {
                float a = 0.0f;
                #pragma unroll
                for (int q = 0; q < 8; ++q) a += S->red_s[q][tid];
                e_s[tid] = a;
            }
            __syncthreads();
        }
        if (tid < 256) {
            float4 a4 = make_float4(0.f, 0.f, 0.f, 0.f);
            #pragma unroll
            for (int r = 0; r < 4; ++r) {
                float ev = e_s[hp * 4 + r];
                a4.x = fmaf(ev, wvp[r].x, a4.x); a4.y = fmaf(ev, wvp[r].y, a4.y);
                a4.z = fmaf(ev, wvp[r].z, a4.z); a4.w = fmaf(ev, wvp[r].w, a4.w);
            }
            a4.x += __shfl_xor_sync(0xffffffffu, a4.x, 16);
            a4.y += __shfl_xor_sync(0xffffffffu, a4.y, 16);
            a4.z += __shfl_xor_sync(0xffffffffu, a4.z, 16);
            a4.w += __shfl_xor_sync(0xffffffffu, a4.w, 16);
            if ((tc & 16) == 0)
                *(float4*)&S->red_f[0][w2][kq * 4] = a4;
        }
        __syncthreads();
        if (tid < HDIM) {
            float v = 0.0f;
            #pragma unroll
            for (int q = 0; q < 8; ++q) v += S->red_f[0][q][tid];
            v += bias_p + S->pe[i][tid];
            S->cache[i][tid] = gelu_exact(v);
        }
        __syncthreads();
    }

    // ---------------- generation priming ----------------
    if (tid == 0) S->x0 = (X0P != nullptr) ? X0P[0] : 7;
    __syncthreads();
    const int x0v = S->x0;

    int nn_reg = 0, nn_next = 0;
    if (tid < 32) {
        nn_reg = NN[(size_t)x0v * CNEI + tid];
        #pragma unroll
        for (int c = 0; c < 4; ++c)
            S->ne_br[tid][c] = NE[(size_t)nn_reg * CNEI + myrank * 4 + c];
    }
    if (tid < 4) S->edge0[tid] = NE[(size_t)x0v * CNEI + myrank * 4 + tid];
    __syncthreads();

    float4 wv[4];
    {
        const float4* Wb = (const float4*)(W + (size_t)S->edge0[g] * (HDIM * HDIM));
        #pragma unroll
        for (int r = 0; r < 4; ++r) wv[r] = Wb[(hp * 4 + r) * 16 + kq];
    }
    float bias_r = 0.0f;
    if (tid < 256) bias_r = Bb[(size_t)S->edge0[tid >> 6] * HDIM + (tid & 63)];

    {   // e for curr = L
        int base = L * (L - 1) / 2;
        if (tid >= 512) {
            int p = (tid >> 6) - 8, k = tid & 63;
            float acc = 0.0f;
            for (int j = p; j < L; j += 8)
                acc = fmaf(S->wts[base + j], S->cache[j][k], acc);
            S->red_s[p][k] = acc;
        }
        __syncthreads();
        if (tid < HDIM) {
            float a = 0.0f;
            #pragma unroll
            for (int q = 0; q < 8; ++q) a += S->red_s[q][tid];
            e_s[tid] = a;
        }
    }
    // all CTAs: mbarriers init'd + primed before any bulk push can arrive
    cluster_sync_all();
    __syncthreads();

    // ---------------- generation loop ----------------
    for (int t = 0; t < T; ++t) {
        const int curr = L + t;
        const int cb   = t & 1;
        const uint32_t mb = cb ? mbar_a1 : mbar_a0;

        // 1) matvec partials for step t
        {
            float4 a4 = make_float4(0.f, 0.f, 0.f, 0.f);
            #pragma unroll
            for (int r = 0; r < 4; ++r) {
                float ev = e_s[hp * 4 + r];
                a4.x = fmaf(ev, wv[r].x, a4.x); a4.y = fmaf(ev, wv[r].y, a4.y);
                a4.z = fmaf(ev, wv[r].z, a4.z); a4.w = fmaf(ev, wv[r].w, a4.w);
            }
            a4.x += __shfl_xor_sync(0xffffffffu, a4.x, 16);
            a4.y += __shfl_xor_sync(0xffffffffu, a4.y, 16);
            a4.z += __shfl_xor_sync(0xffffffffu, a4.z, 16);
            a4.w += __shfl_xor_sync(0xffffffffu, a4.w, 16);
            if ((tc & 16) == 0)
                *(float4*)&S->red_f[g][w2][kq * 4] = a4;
        }
        __syncthreads();   // bar1

        // 2) combine+gelu into local push block | NE branch gathers | pooled partials
        if (tid < 256) {
            if (tid < 32 && t > 0) {
                nn_reg = nn_next;
                int e0 = NE[(size_t)nn_reg * CNEI + myrank * 4 + 0];
                int e1 = NE[(size_t)nn_reg * CNEI + myrank * 4 + 1];
                int e2 = NE[(size_t)nn_reg * CNEI + myrank * 4 + 2];
                int e3 = NE[(size_t)nn_reg * CNEI + myrank * 4 + 3];
                S->ne_br[lane][0] = e0; S->ne_br[lane][1] = e1;
                S->ne_br[lane][2] = e2; S->ne_br[lane][3] = e3;
            }
            int cand = tid >> 6, kk = tid & 63;
            float v = 0.0f;
            #pragma unroll
            for (int q = 0; q < 8; ++q) v += S->red_f[cand][q][kk];
            v += bias_r + S->pe[t][kk];
            float ge = gelu_exact(v);
            S->rx[cb][myrank].vec[cand][kk] = ge;
            float sq = ge * ge;
            #pragma unroll
            for (int off = 16; off > 0; off >>= 1)
                sq += __shfl_xor_sync(0xffffffffu, sq, off);
            if (lane == 0) S->rx[cb][myrank].en[tid >> 5] = sq;
        } else if (tid >= 512 && t + 1 < T) {
            int p = (tid >> 6) - 8, k = tid & 63;
            int base1 = (curr + 1) * curr / 2;
            float acc = 0.0f;
            for (int j = p; j < curr; j += 8)
                acc = fmaf(S->wts[base1 + j], S->cache[j][k], acc);
            S->red_s[p][k] = acc;
        }
        __syncthreads();   // bar2

        // 3) one thread: fence + expect + 7 bulk pushes
        if (tid == 0) {
            asm volatile("fence.proxy.async.shared::cta;" ::: "memory");
            mbar_arrive_expect(mb, EXPECT_TX);
            uint32_t src = (uint32_t)__cvta_generic_to_shared(&S->rx[cb][myrank]);
            #pragma unroll
            for (int r = 0; r < NBLK; ++r) {
                if ((uint32_t)r == myrank) continue;
                bulk_s2s(mapa_u32(src, (uint32_t)r), src, PUSH_BYTES, mapa_u32(mb, (uint32_t)r));
            }
        }

        // 4) wait for all 7 peer blocks
        mbar_wait(mb, (uint32_t)((t >> 1) & 1));

        // 5) per-warp redundant argmax over local energies
        int bi;
        {
            int rr = lane >> 2, cl = lane & 3;
            float2 eh = *(float2*)&S->rx[cb][rr].en[cl * 2];
            float best = eh.x + eh.y;
            bi = lane;
            #pragma unroll
            for (int off = 16; off > 0; off >>= 1) {
                float bo = __shfl_xor_sync(0xffffffffu, best, off);
                int   io = __shfl_xor_sync(0xffffffffu, bi, off);
                if (bo > best || (bo == best && io < bi)) { best = bo; bi = io; }
            }
        }
        if (tid < 32) {
            int y = __shfl_sync(0xffffffffu, nn_reg, bi);
            if (lane == 0) S->tok[t] = y;
            nn_next = NN[(size_t)y * CNEI + lane];
        }

        // 6) next-step weight/bias loads + winner (local!) + e update
        {
            int edge_g = S->ne_br[bi][g];
            const float4* Wb = (const float4*)(W + (size_t)edge_g * (HDIM * HDIM));
            #pragma unroll
            for (int r = 0; r < 4; ++r) wv[r] = Wb[(hp * 4 + r) * 16 + kq];
        }
        if (tid < 256)
            bias_r = Bb[(size_t)S->ne_br[bi][tid >> 6] * HDIM + (tid & 63)];
        if (tid < HDIM) {
            float win = S->rx[cb][bi >> 2].vec[bi & 3][tid];
            S->cache[curr][tid] = win;
            if (t + 1 < T) {
                int base1 = (curr + 1) * curr / 2;
                float ee = 0.0f;
                #pragma unroll
                for (int q = 0; q < 8; ++q) ee += S->red_s[q][tid];
                e_s[tid] = fmaf(S->wts[base1 + curr], win, ee);
            }
        }
        __syncthreads();   // bar4
    }

    // protect in-flight outgoing bulk reads of our smem before exit
    cluster_sync_all();

    // ---------------- output (CTA 0) ----------------
    if (blockIdx.x == 0) {
        int ncache = (L + T) * HDIM;
        for (int i = tid; i < out_size; i += NTHR) {
            float v;
            if (i < ncache) v = S->cache[i >> 6][i & 63];
            else {
                int tt = i - ncache;
                v = (tt < T) ? (float)S->tok[tt] : 0.0f;
            }
            out[i] = v;
        }
    }
}

extern "C" void kernel_launch(void* const* d_in, const int* in_sizes, int n_in,
                              void* d_out, int out_size) {
    const float* W   = (const float*)d_in[0];
    const float* B   = (const float*)d_in[1];
    const float* POS = (const float*)d_in[2];
    const int*   SE  = (const int*)d_in[3];
    const int*   NE  = (const int*)d_in[4];
    const int*   NN  = (const int*)d_in[5];
    const int*   X0  = (n_in > 6) ? (const int*)d_in[6] : nullptr;
    const int*   MNT = (n_in > 7) ? (const int*)d_in[7] : nullptr;
    int L = in_sizes[3];

    cudaFuncSetAttribute(bralm_kernel,
                         cudaFuncAttributeMaxDynamicSharedMemorySize,
                         (int)sizeof(Smem));
    bralm_kernel<<<NBLK, NTHR, sizeof(Smem)>>>(W, B, POS, SE, NE, NN, X0, MNT,
                                               (float*)d_out, out_size, L);
}